// round 8
// baseline (speedup 1.0000x reference)
#include <cuda_runtime.h>
#include <cstdint>
#include <cstddef>

// ===================== problem constants =====================
#define N_ROIS   128
#define N_CH     512
#define FH       37
#define FW       37
#define K_FC6    25088      // 512*7*7
#define NFC      4096

// ===================== static scratch =====================
__device__ __align__(256) float g_pooled[N_ROIS * K_FC6];
__device__ __align__(256) float g_fc6[N_ROIS * NFC];
__device__ __align__(256) float g_fc7[N_ROIS * NFC];

// ===================== simple SIMT fp32 GEMM (unchanged from R6) =====================
__global__ __launch_bounds__(256)
void sgemm_kernel(const float* __restrict__ A, const float* __restrict__ B,
                  const float* __restrict__ bias, float* __restrict__ C,
                  int N, int K, int relu)
{
    __shared__ __align__(16) float As[16][32];
    __shared__ __align__(16) float Bs[16][128];

    const int tx = threadIdx.x & 31;
    const int ty = threadIdx.x >> 5;
    const int m0 = blockIdx.x * 32;
    const int n0 = blockIdx.y * 128;

    float acc[4][4] = {};

    for (int k0 = 0; k0 < K; k0 += 16) {
#pragma unroll
        for (int i = threadIdx.x; i < 512; i += 256) {
            int mm = i >> 4, kk = i & 15;
            As[kk][mm] = A[(size_t)(m0 + mm) * K + k0 + kk];
        }
#pragma unroll
        for (int i = threadIdx.x; i < 2048; i += 256) {
            int nn = i >> 4, kk = i & 15;
            Bs[kk][nn] = B[(size_t)(n0 + nn) * K + k0 + kk];
        }
        __syncthreads();
#pragma unroll
        for (int kk = 0; kk < 16; ++kk) {
            float4 av = *reinterpret_cast<const float4*>(&As[kk][ty * 4]);
            float4 bv = *reinterpret_cast<const float4*>(&Bs[kk][tx * 4]);
            float a[4] = {av.x, av.y, av.z, av.w};
            float b[4] = {bv.x, bv.y, bv.z, bv.w};
#pragma unroll
            for (int i = 0; i < 4; ++i)
#pragma unroll
                for (int j = 0; j < 4; ++j) acc[i][j] += a[i] * b[j];
        }
        __syncthreads();
    }

#pragma unroll
    for (int i = 0; i < 4; ++i)
#pragma unroll
        for (int j = 0; j < 4; ++j) {
            int m = m0 + ty * 4 + i;
            int n = n0 + tx * 4 + j;
            float v = acc[i][j] + bias[n];
            if (relu) v = fmaxf(v, 0.0f);
            C[(size_t)m * N + n] = v;
        }
}

// ===================== RoI max pool — reciprocal-division emulation =====================
// Emulates XLA-CPU fast-math lowering of  t/7  as  t * fl(1/7)  (fl(1/7) = 0x3E124925).
// Bit-exact RN multiply on GPU == RN multiply on CPU, so floor/ceil flips match the
// executed reference exactly (ceil returns m+1 at exact multiples that don't round back).
__global__ void roipool_kernel(const float* __restrict__ x, const float* __restrict__ rois,
                               const int* __restrict__ ridx, float* __restrict__ pooled) {
    const int r = blockIdx.x;
    const float C7 = __uint_as_float(0x3E124925u);  // fl(1/7), round-to-nearest
    __shared__ int hs[7], he[7], ws_[7], we_[7];
    if (threadIdx.x < 7) {
        const int p = threadIdx.x;
        float y1 = rintf(rois[r * 4 + 0] * 0.0625f);
        float x1 = rintf(rois[r * 4 + 1] * 0.0625f);
        float y2 = rintf(rois[r * 4 + 2] * 0.0625f);
        float x2 = rintf(rois[r * 4 + 3] * 0.0625f);
        float rh = fmaxf(y2 - y1 + 1.0f, 1.0f);
        float rw = fmaxf(x2 - x1 + 1.0f, 1.0f);
        float pf = (float)p;
        hs[p]  = (int)fminf(fmaxf(y1 + floorf((pf * rh) * C7), 0.0f), 37.0f);
        he[p]  = (int)fminf(fmaxf(y1 + ceilf(((pf + 1.0f) * rh) * C7), 0.0f), 37.0f);
        ws_[p] = (int)fminf(fmaxf(x1 + floorf((pf * rw) * C7), 0.0f), 37.0f);
        we_[p] = (int)fminf(fmaxf(x1 + ceilf(((pf + 1.0f) * rw) * C7), 0.0f), 37.0f);
    }
    __syncthreads();
    const float* xb = x + (size_t)ridx[r] * N_CH * (FH * FW);
    const float NEG = __int_as_float(0xff800000);
    for (int q = threadIdx.x; q < N_CH * 49; q += blockDim.x) {
        const int c = q / 49;
        const int b = q - c * 49;
        const int ph = b / 7, pw = b - ph * 7;
        const float* xc = xb + c * (FH * FW);
        float mx = NEG;
        for (int h = hs[ph]; h < he[ph]; ++h) {
            const float* xr = xc + h * FW;
            for (int w = ws_[pw]; w < we_[pw]; ++w) mx = fmaxf(mx, xr[w]);
        }
        pooled[(size_t)r * K_FC6 + q] = (mx == NEG) ? 0.0f : mx;
    }
}

// ===================== heads =====================
__global__ __launch_bounds__(256)
void heads_kernel(const float* __restrict__ fc7,
                  const float* __restrict__ Wsc, const float* __restrict__ bsc,
                  const float* __restrict__ Wloc, const float* __restrict__ bloc,
                  float* __restrict__ out) {
    int gw = (blockIdx.x * 256 + threadIdx.x) >> 5;
    int lane = threadIdx.x & 31;
    if (gw >= 128 * 105) return;
    int m = gw / 105, c = gw - m * 105;
    const float* wr = (c < 21) ? (Wsc + (size_t)c * NFC) : (Wloc + (size_t)(c - 21) * NFC);
    const float* arow = fc7 + (size_t)m * NFC;
    float s = 0.0f;
#pragma unroll 4
    for (int k = lane * 4; k < NFC; k += 128) {
        float4 a = *reinterpret_cast<const float4*>(arow + k);
        float4 w = *reinterpret_cast<const float4*>(wr + k);
        s += a.x * w.x + a.y * w.y + a.z * w.z + a.w * w.w;
    }
#pragma unroll
    for (int o = 16; o; o >>= 1) s += __shfl_down_sync(0xffffffffu, s, o);
    if (lane == 0) {
        if (c < 21) out[m * 21 + c] = s + bsc[c];
        else        out[128 * 21 + m * 84 + (c - 21)] = s + bloc[c - 21];
    }
}

// ===================== launch =====================
extern "C" void kernel_launch(void* const* d_in, const int* in_sizes, int n_in,
                              void* d_out, int out_size) {
    const float *x = nullptr, *rois = nullptr, *W1 = nullptr, *b1 = nullptr, *W2 = nullptr,
                *b2 = nullptr, *Wloc = nullptr, *bloc = nullptr, *Wsc = nullptr, *bsc = nullptr;
    const int* ridx = nullptr;
    for (int i = 0; i < n_in; ++i) {
        const int sz = in_sizes[i];
        const float* p = (const float*)d_in[i];
        switch (sz) {
            case 2 * N_CH * FH * FW: x = p; break;
            case N_ROIS * 4:         rois = p; break;
            case N_ROIS:             ridx = (const int*)d_in[i]; break;
            case NFC * K_FC6:        W1 = p; break;
            case NFC * NFC:          W2 = p; break;
            case 84 * NFC:           Wloc = p; break;
            case 21 * NFC:           Wsc = p; break;
            case 84:                 bloc = p; break;
            case 21:                 bsc = p; break;
            case NFC:                if (!b1) b1 = p; else b2 = p; break;
            default: break;
        }
    }
    float* out = (float*)d_out;

    float *pooled, *fc6, *fc7;
    cudaGetSymbolAddress((void**)&pooled, g_pooled);
    cudaGetSymbolAddress((void**)&fc6, g_fc6);
    cudaGetSymbolAddress((void**)&fc7, g_fc7);

    roipool_kernel<<<N_ROIS, 256>>>(x, rois, ridx, pooled);
    {
        dim3 grid(N_ROIS / 32, NFC / 128);
        sgemm_kernel<<<grid, 256>>>(pooled, W1, b1, fc6, NFC, K_FC6, 1);
    }
    {
        dim3 grid(N_ROIS / 32, NFC / 128);
        sgemm_kernel<<<grid, 256>>>(fc6, W2, b2, fc7, NFC, NFC, 1);
    }
    heads_kernel<<<(128 * 105 * 32 + 255) / 256, 256>>>(fc7, Wsc, bsc, Wloc, bloc, out);
}

// round 9
// speedup vs baseline: 4.8558x; 4.8558x over previous
#include <cuda_runtime.h>
#include <cuda_bf16.h>
#include <cstdint>
#include <cstddef>

// ===================== problem constants =====================
#define N_ROIS   128
#define N_CH     512
#define FH       37
#define FW       37
#define K_FC6    25088      // 512*7*7
#define NFC      4096
#define KSPLIT   8

// ===================== static scratch =====================
__device__ __align__(256) float g_pooled[N_ROIS * K_FC6];
__device__ __align__(256) float g_fc6[N_ROIS * NFC];
__device__ __align__(256) float g_fc7[N_ROIS * NFC];
__device__ __align__(256) float g_part[KSPLIT * N_ROIS * NFC];

// ===================== helpers =====================
__device__ __forceinline__ uint32_t smem_u32(const void* p) {
    uint32_t a;
    asm("{ .reg .u64 t; cvta.to.shared.u64 t, %1; cvt.u32.u64 %0, t; }" : "=r"(a) : "l"(p));
    return a;
}

// 2-way bf16 split of a pair of floats -> packed b16x2 words (hi, lo)
__device__ __forceinline__ void split2_pair(float a, float b, uint32_t& h, uint32_t& l) {
    __nv_bfloat16 ha = __float2bfloat16_rn(a), hb = __float2bfloat16_rn(b);
    __nv_bfloat16 la = __float2bfloat16_rn(a - __bfloat162float(ha));
    __nv_bfloat16 lb = __float2bfloat16_rn(b - __bfloat162float(hb));
    h = (uint32_t)__bfloat16_as_ushort(ha) | ((uint32_t)__bfloat16_as_ushort(hb) << 16);
    l = (uint32_t)__bfloat16_as_ushort(la) | ((uint32_t)__bfloat16_as_ushort(lb) << 16);
}

__device__ __forceinline__ void mma16816(float* d, const uint32_t* a, const uint32_t* b) {
    asm volatile(
        "mma.sync.aligned.m16n8k16.row.col.f32.bf16.bf16.f32 "
        "{%0,%1,%2,%3}, {%4,%5,%6,%7}, {%8,%9}, {%0,%1,%2,%3};"
        : "+f"(d[0]), "+f"(d[1]), "+f"(d[2]), "+f"(d[3])
        : "r"(a[0]), "r"(a[1]), "r"(a[2]), "r"(a[3]), "r"(b[0]), "r"(b[1]));
}

#define LDSM4(R, ADDR) \
    asm volatile("ldmatrix.sync.aligned.m8n8.x4.shared.b16 {%0,%1,%2,%3}, [%4];" \
        : "=r"((R)[0]), "=r"((R)[1]), "=r"((R)[2]), "=r"((R)[3]) : "r"(ADDR))

// ===================== GEMM: P[ks][128][*] = A[128,Kchunk] * B[Ntile,Kchunk]^T =====================
// Precision: 2-way bf16 split of both operands; terms hh + hl + lh (residual ~2^-17/product).
// SMEM per stage: A planes H/L [128][40] b16, B planes H/L [128][40] b16. Double buffered.
template <int BN, int WN>
__global__ __launch_bounds__(512, 1)
void gemm_bf16x3(const float* __restrict__ A, const float* __restrict__ B,
                 float* __restrict__ P, int K, int Kchunk, int Ntot, int n_tiles)
{
    extern __shared__ uint32_t sm[];
    constexpr int NTW = WN / 8;
    constexpr int ITB = BN / 128;
    constexpr uint32_t PLA = 128 * 80;       // bytes per A plane
    constexpr uint32_t PLB = (uint32_t)BN * 80;
    constexpr uint32_t A_H = 0, A_L = PLA;
    constexpr uint32_t B_H = 2 * PLA, B_L = B_H + PLB;
    constexpr uint32_t STG_B = 2 * PLA + 2 * PLB;
    constexpr int STG32 = STG_B / 4;

    const int t = threadIdx.x;
    const int wid = t >> 5, lid = t & 31;
    const int wm = wid & 3, wn = wid >> 2;
    const int ntile = blockIdx.x % n_tiles;
    const int ksp = blockIdx.x / n_tiles;
    const int k_begin = ksp * Kchunk;
    const int S = Kchunk >> 5;

    const float* Bt = B + (size_t)(ntile * BN) * K;
    const int ar = t >> 2, ac = t & 3;

    const int aRow = lid & 15;
    const int aK8 = (lid >> 4) & 1;
    const int bRow = (lid & 7) | ((lid & 16) >> 1);
    const int bK8 = (lid >> 3) & 1;

    const uint32_t sb = smem_u32(sm);

    float acc[2][NTW][4];
#pragma unroll
    for (int i = 0; i < 2; ++i)
#pragma unroll
        for (int j = 0; j < NTW; ++j)
#pragma unroll
            for (int q = 0; q < 4; ++q) acc[i][j][q] = 0.0f;

    float4 stA0, stA1;
    float4 stB0[ITB], stB1[ITB];

    auto ldg_stage = [&](int k0) {
        const float* pa = A + (size_t)ar * K + k0 + ac * 8;
        stA0 = *reinterpret_cast<const float4*>(pa);
        stA1 = *reinterpret_cast<const float4*>(pa + 4);
#pragma unroll
        for (int it = 0; it < ITB; ++it) {
            int idx = t + it * 512;
            int br = idx >> 2, bc = idx & 3;
            const float* p = Bt + (size_t)br * K + k0 + bc * 8;
            stB0[it] = *reinterpret_cast<const float4*>(p);
            stB1[it] = *reinterpret_cast<const float4*>(p + 4);
        }
    };

    auto sts_stage = [&](int buf) {
        uint32_t* s = sm + buf * STG32;
        {
            float f[8] = {stA0.x, stA0.y, stA0.z, stA0.w, stA1.x, stA1.y, stA1.z, stA1.w};
            uint32_t hv[4], lv[4];
#pragma unroll
            for (int j = 0; j < 4; ++j) split2_pair(f[2 * j], f[2 * j + 1], hv[j], lv[j]);
            const int o = ar * 20 + ac * 4;
            *reinterpret_cast<uint4*>(s + (A_H / 4) + o) = make_uint4(hv[0], hv[1], hv[2], hv[3]);
            *reinterpret_cast<uint4*>(s + (A_L / 4) + o) = make_uint4(lv[0], lv[1], lv[2], lv[3]);
        }
#pragma unroll
        for (int it = 0; it < ITB; ++it) {
            int idx = t + it * 512;
            int br = idx >> 2, bc = idx & 3;
            float f[8] = {stB0[it].x, stB0[it].y, stB0[it].z, stB0[it].w,
                          stB1[it].x, stB1[it].y, stB1[it].z, stB1[it].w};
            uint32_t hv[4], lv[4];
#pragma unroll
            for (int j = 0; j < 4; ++j) split2_pair(f[2 * j], f[2 * j + 1], hv[j], lv[j]);
            const int o = br * 20 + bc * 4;
            *reinterpret_cast<uint4*>(s + (B_H / 4) + o) = make_uint4(hv[0], hv[1], hv[2], hv[3]);
            *reinterpret_cast<uint4*>(s + (B_L / 4) + o) = make_uint4(lv[0], lv[1], lv[2], lv[3]);
        }
    };

    auto compute = [&](int buf) {
        const uint32_t base = sb + (uint32_t)buf * STG_B;
#pragma unroll
        for (int ks = 0; ks < 2; ++ks) {
            uint32_t ah[2][4], al[2][4];
#pragma unroll
            for (int mt = 0; mt < 2; ++mt) {
                uint32_t off = (uint32_t)(((wm * 32 + mt * 16 + aRow) * 40 + ks * 16 + aK8 * 8) * 2);
                LDSM4(ah[mt], base + A_H + off);
                LDSM4(al[mt], base + A_L + off);
            }
#pragma unroll
            for (int ntp = 0; ntp < NTW / 2; ++ntp) {
                uint32_t boff = (uint32_t)(((wn * WN + ntp * 16 + bRow) * 40 + ks * 16 + bK8 * 8) * 2);
                uint32_t bh[4], bl[4];
                LDSM4(bh, base + B_H + boff);
                LDSM4(bl, base + B_L + boff);
                float* a00 = acc[0][2 * ntp];
                float* a01 = acc[0][2 * ntp + 1];
                float* a10 = acc[1][2 * ntp];
                float* a11 = acc[1][2 * ntp + 1];
                // hh
                mma16816(a00, ah[0], bh);     mma16816(a10, ah[1], bh);
                mma16816(a01, ah[0], bh + 2); mma16816(a11, ah[1], bh + 2);
                // hl
                mma16816(a00, ah[0], bl);     mma16816(a10, ah[1], bl);
                mma16816(a01, ah[0], bl + 2); mma16816(a11, ah[1], bl + 2);
                // lh
                mma16816(a00, al[0], bh);     mma16816(a10, al[1], bh);
                mma16816(a01, al[0], bh + 2); mma16816(a11, al[1], bh + 2);
            }
        }
    };

    ldg_stage(k_begin);
    sts_stage(0);
    __syncthreads();
    for (int s = 0; s < S; ++s) {
        if (s + 1 < S) ldg_stage(k_begin + (s + 1) * 32);
        compute(s & 1);
        if (s + 1 < S) sts_stage((s + 1) & 1);
        __syncthreads();
    }

    const int g = lid >> 2, tig = lid & 3;
    float* Pbase = P + (size_t)(ksp * 128) * Ntot + ntile * BN;
#pragma unroll
    for (int mt = 0; mt < 2; ++mt) {
#pragma unroll
        for (int nt = 0; nt < NTW; ++nt) {
            int row = wm * 32 + mt * 16 + g;
            int col = wn * WN + nt * 8 + tig * 2;
            float* d0 = Pbase + (size_t)row * Ntot + col;
            float* d1 = Pbase + (size_t)(row + 8) * Ntot + col;
            *reinterpret_cast<float2*>(d0) = make_float2(acc[mt][nt][0], acc[mt][nt][1]);
            *reinterpret_cast<float2*>(d1) = make_float2(acc[mt][nt][2], acc[mt][nt][3]);
        }
    }
}

// ===================== RoI max pool — reciprocal-division emulation (LOAD-BEARING) =====================
__global__ void roipool_kernel(const float* __restrict__ x, const float* __restrict__ rois,
                               const int* __restrict__ ridx, float* __restrict__ pooled) {
    const int r = blockIdx.x;
    const float C7 = __uint_as_float(0x3E124925u);  // fl(1/7): matches XLA reciprocal-multiply
    __shared__ int hs[7], he[7], ws_[7], we_[7];
    if (threadIdx.x < 7) {
        const int p = threadIdx.x;
        float y1 = rintf(rois[r * 4 + 0] * 0.0625f);
        float x1 = rintf(rois[r * 4 + 1] * 0.0625f);
        float y2 = rintf(rois[r * 4 + 2] * 0.0625f);
        float x2 = rintf(rois[r * 4 + 3] * 0.0625f);
        float rh = fmaxf(y2 - y1 + 1.0f, 1.0f);
        float rw = fmaxf(x2 - x1 + 1.0f, 1.0f);
        float pf = (float)p;
        hs[p]  = (int)fminf(fmaxf(y1 + floorf((pf * rh) * C7), 0.0f), 37.0f);
        he[p]  = (int)fminf(fmaxf(y1 + ceilf(((pf + 1.0f) * rh) * C7), 0.0f), 37.0f);
        ws_[p] = (int)fminf(fmaxf(x1 + floorf((pf * rw) * C7), 0.0f), 37.0f);
        we_[p] = (int)fminf(fmaxf(x1 + ceilf(((pf + 1.0f) * rw) * C7), 0.0f), 37.0f);
    }
    __syncthreads();
    const float* xb = x + (size_t)ridx[r] * N_CH * (FH * FW);
    const float NEG = __int_as_float(0xff800000);
    for (int q = threadIdx.x; q < N_CH * 49; q += blockDim.x) {
        const int c = q / 49;
        const int b = q - c * 49;
        const int ph = b / 7, pw = b - ph * 7;
        const float* xc = xb + c * (FH * FW);
        float mx = NEG;
        for (int h = hs[ph]; h < he[ph]; ++h) {
            const float* xr = xc + h * FW;
            for (int w = ws_[pw]; w < we_[pw]; ++w) mx = fmaxf(mx, xr[w]);
        }
        pooled[(size_t)r * K_FC6 + q] = (mx == NEG) ? 0.0f : mx;
    }
}

// ===================== reduce: sum split-K partials + bias + relu =====================
__global__ void reduce_kernel(const float* __restrict__ P, const float* __restrict__ bias,
                              float* __restrict__ out) {
    int idx = blockIdx.x * blockDim.x + threadIdx.x;
    if (idx >= 128 * NFC) return;
    int n = idx & (NFC - 1);
    float v = 0.0f;
#pragma unroll
    for (int s = 0; s < KSPLIT; ++s) v += P[(size_t)s * 128 * NFC + idx];
    out[idx] = fmaxf(v + bias[n], 0.0f);
}

// ===================== heads =====================
__global__ __launch_bounds__(256)
void heads_kernel(const float* __restrict__ fc7,
                  const float* __restrict__ Wsc, const float* __restrict__ bsc,
                  const float* __restrict__ Wloc, const float* __restrict__ bloc,
                  float* __restrict__ out) {
    int gw = (blockIdx.x * 256 + threadIdx.x) >> 5;
    int lane = threadIdx.x & 31;
    if (gw >= 128 * 105) return;
    int m = gw / 105, c = gw - m * 105;
    const float* wr = (c < 21) ? (Wsc + (size_t)c * NFC) : (Wloc + (size_t)(c - 21) * NFC);
    const float* arow = fc7 + (size_t)m * NFC;
    float s = 0.0f;
#pragma unroll 4
    for (int k = lane * 4; k < NFC; k += 128) {
        float4 a = *reinterpret_cast<const float4*>(arow + k);
        float4 w = *reinterpret_cast<const float4*>(wr + k);
        s += a.x * w.x + a.y * w.y + a.z * w.z + a.w * w.w;
    }
#pragma unroll
    for (int o = 16; o; o >>= 1) s += __shfl_down_sync(0xffffffffu, s, o);
    if (lane == 0) {
        if (c < 21) out[m * 21 + c] = s + bsc[c];
        else        out[128 * 21 + m * 84 + (c - 21)] = s + bloc[c - 21];
    }
}

// ===================== launch =====================
extern "C" void kernel_launch(void* const* d_in, const int* in_sizes, int n_in,
                              void* d_out, int out_size) {
    const float *x = nullptr, *rois = nullptr, *W1 = nullptr, *b1 = nullptr, *W2 = nullptr,
                *b2 = nullptr, *Wloc = nullptr, *bloc = nullptr, *Wsc = nullptr, *bsc = nullptr;
    const int* ridx = nullptr;
    for (int i = 0; i < n_in; ++i) {
        const int sz = in_sizes[i];
        const float* p = (const float*)d_in[i];
        switch (sz) {
            case 2 * N_CH * FH * FW: x = p; break;
            case N_ROIS * 4:         rois = p; break;
            case N_ROIS:             ridx = (const int*)d_in[i]; break;
            case NFC * K_FC6:        W1 = p; break;
            case NFC * NFC:          W2 = p; break;
            case 84 * NFC:           Wloc = p; break;
            case 21 * NFC:           Wsc = p; break;
            case 84:                 bloc = p; break;
            case 21:                 bsc = p; break;
            case NFC:                if (!b1) b1 = p; else b2 = p; break;
            default: break;
        }
    }
    float* out = (float*)d_out;

    float *pooled, *fc6, *fc7, *part;
    cudaGetSymbolAddress((void**)&pooled, g_pooled);
    cudaGetSymbolAddress((void**)&fc6, g_fc6);
    cudaGetSymbolAddress((void**)&fc7, g_fc7);
    cudaGetSymbolAddress((void**)&part, g_part);

    const int smem_gemm = 2 * (2 * 128 * 80 + 2 * 128 * 80);  // 81920
    cudaFuncSetAttribute((const void*)gemm_bf16x3<128, 32>,
                         cudaFuncAttributeMaxDynamicSharedMemorySize, smem_gemm);

    // 1. RoI max pool
    roipool_kernel<<<N_ROIS, 256>>>(x, rois, ridx, pooled);
    // 2. fc6 (tensor cores, split-K=8, 32 n-tiles)
    gemm_bf16x3<128, 32><<<32 * KSPLIT, 512, smem_gemm>>>(pooled, W1, part, K_FC6, K_FC6 / KSPLIT, NFC, 32);
    reduce_kernel<<<(128 * NFC + 255) / 256, 256>>>(part, b1, fc6);
    // 3. fc7
    gemm_bf16x3<128, 32><<<32 * KSPLIT, 512, smem_gemm>>>(fc6, W2, part, NFC, NFC / KSPLIT, NFC, 32);
    reduce_kernel<<<(128 * NFC + 255) / 256, 256>>>(part, b2, fc7);
    // 4. heads
    heads_kernel<<<(128 * 105 * 32 + 255) / 256, 256>>>(fc7, Wsc, bsc, Wloc, bloc, out);
}